// round 13
// baseline (speedup 1.0000x reference)
#include <cuda_runtime.h>

#define NV   13824   // D*H*W
#define HWV  576     // H*W

// ---------------- scratch (device globals; allocation-free) ----------------
__device__ __align__(16) float g_theta[NV * 64];
__device__ __align__(16) float g_phi[NV * 64];
__device__ __align__(16) float g_gval[NV * 64];
__device__ __align__(16) float g_y0[NV * 64];   // unnormalized exp-weighted sums
__device__ __align__(16) float g_y1[NV * 64];
__device__ __align__(16) float g_y2[NV * 64];
__device__ float g_es0[NV];                     // per-node partial exp sums
__device__ float g_es1[NV];
__device__ float g_es2[NV];
__device__ __align__(16) float g_cross[NV * 64];
__device__ __align__(16) float g_h[NV * 64];
__device__ __align__(16) float g_wT[64 * 192];  // [c][p*64+d]
__device__ __align__(16) float g_rT[64 * 64];   // [g][c]
__device__ float g_statS[32];   // [iter][group]
__device__ float g_statSS[32];

// ---------------- K0: one-time weight transposition ----------------
__global__ __launch_bounds__(256) void k_prep(
    const float* __restrict__ tw, const float* __restrict__ pw,
    const float* __restrict__ gw, const float* __restrict__ rw)
{
    int idx = blockIdx.x * 256 + threadIdx.x;
    if (idx < 12288) {
        int p = idx >> 12, rem = idx & 4095;
        int d = rem >> 6, c = rem & 63;
        const float* w = (p == 0) ? tw : (p == 1) ? pw : gw;
        g_wT[c * 192 + p * 64 + d] = w[d * 64 + c];
    } else if (idx < 12288 + 4096) {
        int rem = idx - 12288;
        int c = rem >> 6, g = rem & 63;
        g_rT[g * 64 + c] = rw[c * 64 + g];
    }
}

// ---------------- K1: fused theta/phi/g projection (32 nodes/block) ----------------
// iter==1 additionally applies iter-0 GroupNorm + residual while loading h,
// stores g_h; block 0 zeros this iteration's GN stat slots.
__global__ __launch_bounds__(256) void k_proj(
    const float* __restrict__ x, int iter,
    const float* __restrict__ tb, const float* __restrict__ pb,
    const float* __restrict__ gb,
    const float* __restrict__ gng, const float* __restrict__ gnb)
{
    extern __shared__ float dsm[];
    float* hs = dsm;                  // [c][nl], stride 32 (2048)
    float* ws = dsm + 2048;           // [c][p*64+d], stride 192 (12288)
    float* sm_m  = dsm + 14336;       // 16
    float* sm_rs = dsm + 14352;       // 16

    const int t = threadIdx.x;
    const int n0 = blockIdx.x * 32;

    if (iter) {
        if (t < 16) {
            const float invc = 1.f / (4.f * NV);
            float m = g_statS[t] * invc;
            float var = g_statSS[t] * invc - m * m;
            sm_m[t] = m;
            sm_rs[t] = rsqrtf(var + 1e-5f);
        }
        __syncthreads();
    }
    if (blockIdx.x == 0 && t < 16) {
        g_statS [iter * 16 + t] = 0.f;
        g_statSS[iter * 16 + t] = 0.f;
    }

    // load h tile: hs layout is linear copy of (c, nl) tile
    if (iter == 0) {
        for (int v = t; v < 512; v += 256) {
            int c = v >> 3, nl4 = (v & 7) * 4;
            *(float4*)&hs[v * 4] = *(const float4*)&x[(size_t)c * NV + n0 + nl4];
        }
    } else {
        for (int v = t; v < 512; v += 256) {
            int c = v >> 3, nl4 = (v & 7) * 4;
            int g = c >> 2;
            size_t gi = (size_t)c * NV + n0 + nl4;
            float4 xv = *(const float4*)&x[gi];
            float4 cv = *(const float4*)&g_cross[gi];
            float sc = sm_rs[g] * gng[c];
            float off = gnb[c] - sm_m[g] * sc;
            float4 hv;
            hv.x = xv.x + cv.x * sc + off;
            hv.y = xv.y + cv.y * sc + off;
            hv.z = xv.z + cv.z * sc + off;
            hv.w = xv.w + cv.w * sc + off;
            *(float4*)&hs[v * 4] = hv;
            *(float4*)&g_h[gi] = hv;
        }
    }

    // weights: straight linear float4 copy (pre-transposed by k_prep)
    {
        const float4* wt4 = (const float4*)g_wT;
        float4* ws4 = (float4*)ws;
        for (int v = t; v < 3072; v += 256) ws4[v] = wt4[v];
    }
    __syncthreads();

    const int nl0 = (t & 7) * 4;     // 8 node groups of 4
    const int d0  = (t >> 3) * 2;    // 32 d-groups of 2 (per projection)

    float acc[3][2][4];              // [proj][di][ni]
    {
        const float* bs[3] = {tb, pb, gb};
        #pragma unroll
        for (int p = 0; p < 3; p++)
            #pragma unroll
            for (int di = 0; di < 2; di++) {
                float bb = bs[p][d0 + di];
                #pragma unroll
                for (int ni = 0; ni < 4; ni++) acc[p][di][ni] = bb;
            }
    }

    #pragma unroll 4
    for (int c = 0; c < 64; c++) {
        float4 hv = *(const float4*)&hs[c * 32 + nl0];
        float ha[4] = {hv.x, hv.y, hv.z, hv.w};
        #pragma unroll
        for (int p = 0; p < 3; p++) {
            float2 wv = *(const float2*)&ws[c * 192 + p * 64 + d0];
            #pragma unroll
            for (int ni = 0; ni < 4; ni++) {
                acc[p][0][ni] += ha[ni] * wv.x;
                acc[p][1][ni] += ha[ni] * wv.y;
            }
        }
    }

    float* outs[3] = {g_theta, g_phi, g_gval};
    #pragma unroll
    for (int p = 0; p < 3; p++)
        #pragma unroll
        for (int ni = 0; ni < 4; ni++)
            *(float2*)&outs[p][(size_t)(n0 + nl0 + ni) * 64 + d0] =
                make_float2(acc[p][0][ni], acc[p][1][ni]);
}

// line geometry: fam 0 = depth line (incl self), 1 = H line, 2 = W line
__device__ __forceinline__ void line_geom(int fam, int line, int& base, int& stride)
{
    if (fam == 0)      { base = line; stride = HWV; }
    else if (fam == 1) { base = (line / 24) * HWV + (line % 24); stride = 24; }
    else               { base = line * 24; stride = 1; }
}

// ---------------- K2: fused scores + exp + merge per (line, fam) ----------------
// gram = theta . phi^T (24x24), a = exp(gram) (diag zeroed for fam 1/2),
// y_fam = a . g (unnormalized), es_fam = row sums of a.
__global__ __launch_bounds__(128) void k_attn()
{
    __shared__ float th[24][68];
    __shared__ float ph[24][68];
    __shared__ float gs[24][68];
    __shared__ float as[24][25];
    const int t = threadIdx.x;
    int base, stride;
    line_geom(blockIdx.y, blockIdx.x, base, stride);
    const int fam = blockIdx.y;

    // load theta/phi/g tiles: 3 x 24 x 64 floats, float4 over d
    for (int v = t; v < 1152; v += 128) {
        int arr = v / 384;
        int rem = v - arr * 384;
        int p = rem >> 4, d4 = (rem & 15) * 4;
        size_t gi = (size_t)(base + p * stride) * 64 + d4;
        float4 val = (arr == 0) ? *(const float4*)&g_theta[gi]
                   : (arr == 1) ? *(const float4*)&g_phi[gi]
                                : *(const float4*)&g_gval[gi];
        float* dst = (arr == 0) ? &th[p][d4] : (arr == 1) ? &ph[p][d4] : &gs[p][d4];
        *(float4*)dst = val;
    }
    __syncthreads();

    // gram phase: 64 tiles of 3x3 over (24x24); thread pairs split c-dim
    {
        const int tile = t >> 1;             // 0..63
        const int ch = (t & 1) * 32;         // c-half base
        const int r0 = (tile >> 3) * 3;
        const int q0 = (tile & 7) * 3;
        float acc[3][3] = {};
        #pragma unroll
        for (int cc = 0; cc < 8; cc++) {
            int c4 = ch + cc * 4;
            float4 tv[3], pv[3];
            #pragma unroll
            for (int r = 0; r < 3; r++) tv[r] = *(const float4*)&th[r0 + r][c4];
            #pragma unroll
            for (int q = 0; q < 3; q++) pv[q] = *(const float4*)&ph[q0 + q][c4];
            #pragma unroll
            for (int r = 0; r < 3; r++)
                #pragma unroll
                for (int q = 0; q < 3; q++)
                    acc[r][q] += tv[r].x * pv[q].x + tv[r].y * pv[q].y +
                                 tv[r].z * pv[q].z + tv[r].w * pv[q].w;
        }
        // combine c-halves (t and t^1 are same warp)
        #pragma unroll
        for (int r = 0; r < 3; r++)
            #pragma unroll
            for (int q = 0; q < 3; q++)
                acc[r][q] += __shfl_xor_sync(0xffffffffu, acc[r][q], 1);
        if ((t & 1) == 0) {
            #pragma unroll
            for (int r = 0; r < 3; r++)
                #pragma unroll
                for (int q = 0; q < 3; q++) {
                    int row = r0 + r, col = q0 + q;
                    as[row][col] = (fam != 0 && col == row) ? 0.f : __expf(acc[r][q]);
                }
        }
    }
    __syncthreads();

    // per-node partial exp sums
    if (t < 24) {
        float s = 0.f;
        #pragma unroll
        for (int q = 0; q < 24; q++) s += as[t][q];
        float* es = (fam == 0) ? g_es0 : (fam == 1) ? g_es1 : g_es2;
        es[base + t * stride] = s;
    }

    // merge phase: y = a . g
    const int rg = t >> 4;          // 8 row groups of 3 nodes
    const int d0 = (t & 15) * 4;    // 16 col groups of 4 dims
    float acc[3][4] = {};
    #pragma unroll
    for (int l = 0; l < 24; l++) {
        float4 gv = *(const float4*)&gs[l][d0];
        #pragma unroll
        for (int r = 0; r < 3; r++) {
            float a = as[rg * 3 + r][l];
            acc[r][0] += a * gv.x; acc[r][1] += a * gv.y;
            acc[r][2] += a * gv.z; acc[r][3] += a * gv.w;
        }
    }
    float* yout = (fam == 0) ? g_y0 : (fam == 1) ? g_y1 : g_y2;
    #pragma unroll
    for (int r = 0; r < 3; r++) {
        int node = base + (rg * 3 + r) * stride;
        *(float4*)&yout[(size_t)node * 64 + d0] =
            make_float4(acc[r][0], acc[r][1], acc[r][2], acc[r][3]);
    }
}

// ---------------- K3: normalize + output projection + GroupNorm stats ----------------
__global__ __launch_bounds__(256) void k_cross(
    const float* __restrict__ rb, int iter)
{
    __shared__ float ys[64 * 36];   // [g][node_local]
    __shared__ float rs[64 * 72];   // [g][c]
    __shared__ float inv_s[32];
    const int t = threadIdx.x;
    const int n0 = blockIdx.x * 32;

    if (t < 32) {
        int n = n0 + t;
        inv_s[t] = 1.f / (g_es0[n] + g_es1[n] + g_es2[n]);
    }
    __syncthreads();

    // ys: 64 dims x 32 nodes, normalized; float4 over g, transpose-scatter
    for (int v = t; v < 512; v += 256) {
        int nl = v >> 4, g4 = (v & 15) * 4;
        size_t gi = (size_t)(n0 + nl) * 64 + g4;
        float inv = inv_s[nl];
        float4 a = *(const float4*)&g_y0[gi];
        float4 b = *(const float4*)&g_y1[gi];
        float4 c = *(const float4*)&g_y2[gi];
        ys[(g4 + 0) * 36 + nl] = (a.x + b.x + c.x) * inv;
        ys[(g4 + 1) * 36 + nl] = (a.y + b.y + c.y) * inv;
        ys[(g4 + 2) * 36 + nl] = (a.z + b.z + c.z) * inv;
        ys[(g4 + 3) * 36 + nl] = (a.w + b.w + c.w) * inv;
    }
    // rs: pre-transposed, float4 copy with stride re-pack 64 -> 72
    for (int v = t; v < 1024; v += 256) {
        int g = v >> 4, c4 = (v & 15) * 4;
        *(float4*)&rs[g * 72 + c4] = *(const float4*)&g_rT[g * 64 + c4];
    }
    __syncthreads();

    const int nl0 = (t & 7) * 4;     // 8 node groups of 4
    const int c0  = (t >> 3) * 2;    // 32 channel groups of 2
    float acc[2][4];
    #pragma unroll
    for (int ci = 0; ci < 2; ci++) {
        float bb = rb[c0 + ci];
        #pragma unroll
        for (int ni = 0; ni < 4; ni++) acc[ci][ni] = bb;
    }
    #pragma unroll 8
    for (int gg = 0; gg < 64; gg++) {
        float4 yv = *(const float4*)&ys[gg * 36 + nl0];
        float2 rv = *(const float2*)&rs[gg * 72 + c0];
        float ya[4] = {yv.x, yv.y, yv.z, yv.w};
        #pragma unroll
        for (int ni = 0; ni < 4; ni++) {
            acc[0][ni] += rv.x * ya[ni];
            acc[1][ni] += rv.y * ya[ni];
        }
    }

    float s = 0.f, ss = 0.f;
    #pragma unroll
    for (int ci = 0; ci < 2; ci++) {
        *(float4*)&g_cross[(size_t)(c0 + ci) * NV + n0 + nl0] =
            make_float4(acc[ci][0], acc[ci][1], acc[ci][2], acc[ci][3]);
        #pragma unroll
        for (int ni = 0; ni < 4; ni++) {
            s += acc[ci][ni];
            ss += acc[ci][ni] * acc[ci][ni];
        }
    }
    // threads with equal t>>4 share GN group g = t>>4 (channels 4g..4g+3)
    #pragma unroll
    for (int o = 8; o; o >>= 1) {
        s  += __shfl_xor_sync(0xffffffffu, s, o);
        ss += __shfl_xor_sync(0xffffffffu, ss, o);
    }
    if ((t & 15) == 0) {
        atomicAdd(&g_statS [iter * 16 + (t >> 4)], s);
        atomicAdd(&g_statSS[iter * 16 + (t >> 4)], ss);
    }
}

// ---------------- K4: final GN apply + residual + BN + ReLU (float4) ----------------
__global__ __launch_bounds__(256) void k_final(
    const float* __restrict__ gng, const float* __restrict__ gnb,
    const float* __restrict__ bng, const float* __restrict__ bnb,
    const float* __restrict__ bnm, const float* __restrict__ bnv,
    float* __restrict__ out)
{
    int i4 = blockIdx.x * 256 + threadIdx.x;
    int idx = i4 * 4;
    int c = idx / NV;
    int g = c >> 2;
    const float invc = 1.f / (4.f * NV);
    float m   = g_statS [16 + g] * invc;
    float var = g_statSS[16 + g] * invc - m * m;
    float rstd = rsqrtf(var + 1e-5f);
    float ga = gng[c], gb = gnb[c];
    float bsc = rsqrtf(bnv[c] + 1e-5f) * bng[c];
    float bm = bnm[c], bb = bnb[c];

    float4 hv = *(const float4*)&g_h[idx];
    float4 cv = *(const float4*)&g_cross[idx];
    float ha[4] = {hv.x, hv.y, hv.z, hv.w};
    float ca[4] = {cv.x, cv.y, cv.z, cv.w};
    float oa[4];
    #pragma unroll
    for (int i = 0; i < 4; i++) {
        float v = ha[i] + (ca[i] - m) * rstd * ga + gb;
        float o = (v - bm) * bsc + bb;
        oa[i] = fmaxf(o, 0.f);
    }
    *(float4*)&out[idx] = make_float4(oa[0], oa[1], oa[2], oa[3]);
}

// ---------------- launch ----------------
extern "C" void kernel_launch(void* const* d_in, const int* in_sizes, int n_in,
                              void* d_out, int out_size)
{
    const float* x        = (const float*)d_in[0];
    // d_in[1] = nbr_idx (int32) — neighbor structure derived analytically, unused
    const float* phi_w    = (const float*)d_in[2];
    const float* phi_b    = (const float*)d_in[3];
    const float* theta_w  = (const float*)d_in[4];
    const float* theta_b  = (const float*)d_in[5];
    const float* G_w      = (const float*)d_in[6];
    const float* G_b      = (const float*)d_in[7];
    const float* r_w      = (const float*)d_in[8];
    const float* r_b      = (const float*)d_in[9];
    const float* gn_gamma = (const float*)d_in[10];
    const float* gn_beta  = (const float*)d_in[11];
    const float* bn_gamma = (const float*)d_in[12];
    const float* bn_beta  = (const float*)d_in[13];
    const float* bn_mean  = (const float*)d_in[14];
    const float* bn_var   = (const float*)d_in[15];
    float* out = (float*)d_out;

    const int proj_smem = (2048 + 12288 + 32) * sizeof(float);  // 57472 B
    static bool attr_set = false;
    if (!attr_set) {
        cudaFuncSetAttribute(k_proj, cudaFuncAttributeMaxDynamicSharedMemorySize, proj_smem);
        attr_set = true;
    }

    k_prep<<<64, 256>>>(theta_w, phi_w, G_w, r_w);
    dim3 gline(576, 3);
    for (int it = 0; it < 2; it++) {
        k_proj<<<NV / 32, 256, proj_smem>>>(x, it, theta_b, phi_b, G_b,
                                            gn_gamma, gn_beta);
        k_attn<<<gline, 128>>>();
        k_cross<<<NV / 32, 256>>>(r_b, it);
    }
    k_final<<<(64 * NV) / 1024, 256>>>(gn_gamma + 64, gn_beta + 64,
                                       bn_gamma, bn_beta, bn_mean, bn_var, out);
}

// round 14
// speedup vs baseline: 1.0392x; 1.0392x over previous
#include <cuda_runtime.h>

#define NV   13824   // D*H*W
#define HWV  576     // H*W

// ---------------- scratch (device globals; allocation-free) ----------------
__device__ __align__(16) float g_theta[NV * 64];
__device__ __align__(16) float g_phi[NV * 64];
__device__ __align__(16) float g_gval[NV * 64];
__device__ __align__(16) float g_f[NV * 72];    // [node][fam*24+col], diag slots included
__device__ __align__(16) float g_y0[NV * 64];   // unnormalized exp-weighted sums
__device__ __align__(16) float g_y1[NV * 64];
__device__ __align__(16) float g_y2[NV * 64];
__device__ float g_es0[NV];                     // per-node partial exp sums
__device__ float g_es1[NV];
__device__ float g_es2[NV];
__device__ __align__(16) float g_cross[NV * 64];
__device__ __align__(16) float g_h[NV * 64];
__device__ __align__(16) float g_wT[64 * 192];  // [c][p*64+d]
__device__ float g_statS[32];   // [iter][group]
__device__ float g_statSS[32];

// ---------------- K0: one-time weight transposition (theta/phi/G only) ----------------
__global__ __launch_bounds__(256) void k_prep(
    const float* __restrict__ tw, const float* __restrict__ pw,
    const float* __restrict__ gw)
{
    int idx = blockIdx.x * 256 + threadIdx.x;
    if (idx < 12288) {
        int p = idx >> 12, rem = idx & 4095;
        int d = rem >> 6, c = rem & 63;
        const float* w = (p == 0) ? tw : (p == 1) ? pw : gw;
        g_wT[c * 192 + p * 64 + d] = w[d * 64 + c];
    }
}

// ---------------- K1: fused theta/phi/g projection (32 nodes/block) ----------------
__global__ __launch_bounds__(256) void k_proj(
    const float* __restrict__ x, int iter,
    const float* __restrict__ tb, const float* __restrict__ pb,
    const float* __restrict__ gb,
    const float* __restrict__ gng, const float* __restrict__ gnb)
{
    extern __shared__ float dsm[];
    float* hs = dsm;                  // [c][nl], stride 32 (2048)
    float* ws = dsm + 2048;           // [c][p*64+d], stride 192 (12288)
    float* sm_m  = dsm + 14336;       // 16
    float* sm_rs = dsm + 14352;       // 16

    const int t = threadIdx.x;
    const int n0 = blockIdx.x * 32;

    if (iter) {
        if (t < 16) {
            const float invc = 1.f / (4.f * NV);
            float m = g_statS[t] * invc;
            float var = g_statSS[t] * invc - m * m;
            sm_m[t] = m;
            sm_rs[t] = rsqrtf(var + 1e-5f);
        }
        __syncthreads();
    }
    if (blockIdx.x == 0 && t < 16) {
        g_statS [iter * 16 + t] = 0.f;
        g_statSS[iter * 16 + t] = 0.f;
    }

    if (iter == 0) {
        for (int v = t; v < 512; v += 256) {
            int c = v >> 3, nl4 = (v & 7) * 4;
            *(float4*)&hs[v * 4] = *(const float4*)&x[(size_t)c * NV + n0 + nl4];
        }
    } else {
        for (int v = t; v < 512; v += 256) {
            int c = v >> 3, nl4 = (v & 7) * 4;
            int g = c >> 2;
            size_t gi = (size_t)c * NV + n0 + nl4;
            float4 xv = *(const float4*)&x[gi];
            float4 cv = *(const float4*)&g_cross[gi];
            float sc = sm_rs[g] * gng[c];
            float off = gnb[c] - sm_m[g] * sc;
            float4 hv;
            hv.x = xv.x + cv.x * sc + off;
            hv.y = xv.y + cv.y * sc + off;
            hv.z = xv.z + cv.z * sc + off;
            hv.w = xv.w + cv.w * sc + off;
            *(float4*)&hs[v * 4] = hv;
            *(float4*)&g_h[gi] = hv;
        }
    }

    {
        const float4* wt4 = (const float4*)g_wT;
        float4* ws4 = (float4*)ws;
        for (int v = t; v < 3072; v += 256) ws4[v] = wt4[v];
    }
    __syncthreads();

    const int nl0 = (t & 7) * 4;
    const int d0  = (t >> 3) * 2;

    float acc[3][2][4];
    {
        const float* bs[3] = {tb, pb, gb};
        #pragma unroll
        for (int p = 0; p < 3; p++)
            #pragma unroll
            for (int di = 0; di < 2; di++) {
                float bb = bs[p][d0 + di];
                #pragma unroll
                for (int ni = 0; ni < 4; ni++) acc[p][di][ni] = bb;
            }
    }

    #pragma unroll 4
    for (int c = 0; c < 64; c++) {
        float4 hv = *(const float4*)&hs[c * 32 + nl0];
        float ha[4] = {hv.x, hv.y, hv.z, hv.w};
        #pragma unroll
        for (int p = 0; p < 3; p++) {
            float2 wv = *(const float2*)&ws[c * 192 + p * 64 + d0];
            #pragma unroll
            for (int ni = 0; ni < 4; ni++) {
                acc[p][0][ni] += ha[ni] * wv.x;
                acc[p][1][ni] += ha[ni] * wv.y;
            }
        }
    }

    float* outs[3] = {g_theta, g_phi, g_gval};
    #pragma unroll
    for (int p = 0; p < 3; p++)
        #pragma unroll
        for (int ni = 0; ni < 4; ni++)
            *(float2*)&outs[p][(size_t)(n0 + nl0 + ni) * 64 + d0] =
                make_float2(acc[p][0][ni], acc[p][1][ni]);
}

// line geometry: fam 0 = depth line (incl self), 1 = H line, 2 = W line
__device__ __forceinline__ void line_geom(int fam, int line, int& base, int& stride)
{
    if (fam == 0)      { base = line; stride = HWV; }
    else if (fam == 1) { base = (line / 24) * HWV + (line % 24); stride = 24; }
    else               { base = line * 24; stride = 1; }
}

// ---------------- K2: attention scores as 24x24 line grams (raw logits) ----------------
__global__ __launch_bounds__(64) void k_scores()
{
    __shared__ float th[24][68];
    __shared__ float ph[24][68];
    const int t = threadIdx.x;
    int base, stride;
    line_geom(blockIdx.y, blockIdx.x, base, stride);
    const int fam24 = blockIdx.y * 24;

    for (int idx = t; idx < 1536; idx += 64) {
        int p = idx >> 6, d = idx & 63;
        int node = base + p * stride;
        th[p][d] = g_theta[(size_t)node * 64 + d];
        ph[p][d] = g_phi[(size_t)node * 64 + d];
    }
    __syncthreads();

    const int r0 = (t >> 3) * 3;
    const int q0 = (t & 7) * 3;
    float acc[3][3] = {};
    #pragma unroll
    for (int cc = 0; cc < 16; cc++) {
        float4 tv[3], pv[3];
        #pragma unroll
        for (int r = 0; r < 3; r++) tv[r] = *(const float4*)&th[r0 + r][cc * 4];
        #pragma unroll
        for (int q = 0; q < 3; q++) pv[q] = *(const float4*)&ph[q0 + q][cc * 4];
        #pragma unroll
        for (int r = 0; r < 3; r++)
            #pragma unroll
            for (int q = 0; q < 3; q++)
                acc[r][q] += tv[r].x * pv[q].x + tv[r].y * pv[q].y +
                             tv[r].z * pv[q].z + tv[r].w * pv[q].w;
    }

    #pragma unroll
    for (int r = 0; r < 3; r++) {
        int node = base + (r0 + r) * stride;
        #pragma unroll
        for (int q = 0; q < 3; q++)
            g_f[(size_t)node * 72 + fam24 + q0 + q] = acc[r][q];
    }
}

// ---------------- K3: unnormalized exp-weighted merge (per family) ----------------
__global__ __launch_bounds__(128) void k_merge()
{
    __shared__ float gs[24][68];
    __shared__ float as[24][25];
    const int t = threadIdx.x;
    int base, stride;
    line_geom(blockIdx.y, blockIdx.x, base, stride);
    const int fam = blockIdx.y;

    for (int idx = t; idx < 1536; idx += 128) {
        int p = idx >> 6, d = idx & 63;
        gs[p][d] = g_gval[(size_t)(base + p * stride) * 64 + d];
    }
    for (int v = t; v < 144; v += 128) {
        int p = v / 6, q4 = (v - p * 6) * 4;
        float4 fv = *(const float4*)&g_f[(size_t)(base + p * stride) * 72 + fam * 24 + q4];
        float e[4] = {__expf(fv.x), __expf(fv.y), __expf(fv.z), __expf(fv.w)};
        #pragma unroll
        for (int c = 0; c < 4; c++) {
            int q = q4 + c;
            as[p][q] = (fam != 0 && q == p) ? 0.f : e[c];
        }
    }
    __syncthreads();

    if (t < 24) {
        float s = 0.f;
        #pragma unroll
        for (int q = 0; q < 24; q++) s += as[t][q];
        float* es = (fam == 0) ? g_es0 : (fam == 1) ? g_es1 : g_es2;
        es[base + t * stride] = s;
    }

    const int rg = t >> 4;
    const int d0 = (t & 15) * 4;
    float acc[3][4] = {};
    #pragma unroll
    for (int l = 0; l < 24; l++) {
        float4 gv = *(const float4*)&gs[l][d0];
        #pragma unroll
        for (int r = 0; r < 3; r++) {
            float a = as[rg * 3 + r][l];
            acc[r][0] += a * gv.x; acc[r][1] += a * gv.y;
            acc[r][2] += a * gv.z; acc[r][3] += a * gv.w;
        }
    }
    float* yout = (fam == 0) ? g_y0 : (fam == 1) ? g_y1 : g_y2;
    #pragma unroll
    for (int r = 0; r < 3; r++) {
        int node = base + (rg * 3 + r) * stride;
        *(float4*)&yout[(size_t)node * 64 + d0] =
            make_float4(acc[r][0], acc[r][1], acc[r][2], acc[r][3]);
    }
}

// ---------------- K4: normalize + output projection + GroupNorm stats ----------------
// Node-major ys (stride 68), native-layout rs (stride 68); strided node tiling
// makes every smem access conflict-free.
__global__ __launch_bounds__(256) void k_cross(
    const float* __restrict__ rw, const float* __restrict__ rb, int iter)
{
    __shared__ float ys[32 * 68];   // [nl][g]
    __shared__ float rs[64 * 68];   // [c][g]
    __shared__ float inv_s[32];
    const int t = threadIdx.x;
    const int n0 = blockIdx.x * 32;

    if (t < 32) {
        int n = n0 + t;
        inv_s[t] = 1.f / (g_es0[n] + g_es1[n] + g_es2[n]);
    }
    __syncthreads();

    // ys: linear float4 loads, normalized, linear float4 stores (conflict-free)
    for (int v = t; v < 512; v += 256) {
        int nl = v >> 4, g4 = (v & 15) * 4;
        size_t gi = (size_t)(n0 + nl) * 64 + g4;
        float inv = inv_s[nl];
        float4 a = *(const float4*)&g_y0[gi];
        float4 b = *(const float4*)&g_y1[gi];
        float4 c = *(const float4*)&g_y2[gi];
        *(float4*)&ys[nl * 68 + g4] =
            make_float4((a.x + b.x + c.x) * inv, (a.y + b.y + c.y) * inv,
                        (a.z + b.z + c.z) * inv, (a.w + b.w + c.w) * inv);
    }
    // rs: native rw layout [c][g], pure linear float4 copy (no transpose)
    for (int v = t; v < 1024; v += 256) {
        int c = v >> 4, g4 = (v & 15) * 4;
        *(float4*)&rs[c * 68 + g4] = *(const float4*)&rw[c * 64 + g4];
    }
    __syncthreads();

    const int q  = t & 7;            // node lane: handles nodes q, q+8, q+16, q+24
    const int c0 = (t >> 3) * 2;     // channel pair
    float acc[2][4];
    #pragma unroll
    for (int ci = 0; ci < 2; ci++) {
        float bb = rb[c0 + ci];
        #pragma unroll
        for (int ni = 0; ni < 4; ni++) acc[ci][ni] = bb;
    }

    #pragma unroll 4
    for (int g4 = 0; g4 < 64; g4 += 4) {
        float4 ra = *(const float4*)&rs[c0 * 68 + g4];
        float4 rbv = *(const float4*)&rs[(c0 + 1) * 68 + g4];
        #pragma unroll
        for (int ni = 0; ni < 4; ni++) {
            float4 yv = *(const float4*)&ys[(q + 8 * ni) * 68 + g4];
            acc[0][ni] += ra.x * yv.x + ra.y * yv.y + ra.z * yv.z + ra.w * yv.w;
            acc[1][ni] += rbv.x * yv.x + rbv.y * yv.y + rbv.z * yv.z + rbv.w * yv.w;
        }
    }

    float s = 0.f, ss = 0.f;
    #pragma unroll
    for (int ci = 0; ci < 2; ci++) {
        #pragma unroll
        for (int ni = 0; ni < 4; ni++) {
            g_cross[(size_t)(c0 + ci) * NV + n0 + q + 8 * ni] = acc[ci][ni];
            s += acc[ci][ni];
            ss += acc[ci][ni] * acc[ci][ni];
        }
    }
    // threads with equal t>>4 share GN group g = t>>4 (channels 4g..4g+3, all nodes)
    #pragma unroll
    for (int o = 8; o; o >>= 1) {
        s  += __shfl_xor_sync(0xffffffffu, s, o);
        ss += __shfl_xor_sync(0xffffffffu, ss, o);
    }
    if ((t & 15) == 0) {
        atomicAdd(&g_statS [iter * 16 + (t >> 4)], s);
        atomicAdd(&g_statSS[iter * 16 + (t >> 4)], ss);
    }
}

// ---------------- K5: final GN apply + residual + BN + ReLU (float4) ----------------
__global__ __launch_bounds__(256) void k_final(
    const float* __restrict__ gng, const float* __restrict__ gnb,
    const float* __restrict__ bng, const float* __restrict__ bnb,
    const float* __restrict__ bnm, const float* __restrict__ bnv,
    float* __restrict__ out)
{
    int i4 = blockIdx.x * 256 + threadIdx.x;
    int idx = i4 * 4;
    int c = idx / NV;
    int g = c >> 2;
    const float invc = 1.f / (4.f * NV);
    float m   = g_statS [16 + g] * invc;
    float var = g_statSS[16 + g] * invc - m * m;
    float rstd = rsqrtf(var + 1e-5f);
    float ga = gng[c], gb = gnb[c];
    float bsc = rsqrtf(bnv[c] + 1e-5f) * bng[c];
    float bm = bnm[c], bb = bnb[c];

    float4 hv = *(const float4*)&g_h[idx];
    float4 cv = *(const float4*)&g_cross[idx];
    float ha[4] = {hv.x, hv.y, hv.z, hv.w};
    float ca[4] = {cv.x, cv.y, cv.z, cv.w};
    float oa[4];
    #pragma unroll
    for (int i = 0; i < 4; i++) {
        float v = ha[i] + (ca[i] - m) * rstd * ga + gb;
        float o = (v - bm) * bsc + bb;
        oa[i] = fmaxf(o, 0.f);
    }
    *(float4*)&out[idx] = make_float4(oa[0], oa[1], oa[2], oa[3]);
}

// ---------------- launch ----------------
extern "C" void kernel_launch(void* const* d_in, const int* in_sizes, int n_in,
                              void* d_out, int out_size)
{
    const float* x        = (const float*)d_in[0];
    // d_in[1] = nbr_idx (int32) — neighbor structure derived analytically, unused
    const float* phi_w    = (const float*)d_in[2];
    const float* phi_b    = (const float*)d_in[3];
    const float* theta_w  = (const float*)d_in[4];
    const float* theta_b  = (const float*)d_in[5];
    const float* G_w      = (const float*)d_in[6];
    const float* G_b      = (const float*)d_in[7];
    const float* r_w      = (const float*)d_in[8];
    const float* r_b      = (const float*)d_in[9];
    const float* gn_gamma = (const float*)d_in[10];
    const float* gn_beta  = (const float*)d_in[11];
    const float* bn_gamma = (const float*)d_in[12];
    const float* bn_beta  = (const float*)d_in[13];
    const float* bn_mean  = (const float*)d_in[14];
    const float* bn_var   = (const float*)d_in[15];
    float* out = (float*)d_out;

    const int proj_smem = (2048 + 12288 + 32) * sizeof(float);  // 57472 B
    static bool attr_set = false;
    if (!attr_set) {
        cudaFuncSetAttribute(k_proj, cudaFuncAttributeMaxDynamicSharedMemorySize, proj_smem);
        attr_set = true;
    }

    k_prep<<<48, 256>>>(theta_w, phi_w, G_w);
    dim3 gline(576, 3);
    for (int it = 0; it < 2; it++) {
        k_proj<<<NV / 32, 256, proj_smem>>>(x, it, theta_b, phi_b, G_b,
                                            gn_gamma, gn_beta);
        k_scores<<<gline, 64>>>();
        k_merge<<<gline, 128>>>();
        k_cross<<<NV / 32, 256>>>(r_w, r_b, it);
    }
    k_final<<<(64 * NV) / 1024, 256>>>(gn_gamma + 64, gn_beta + 64,
                                       bn_gamma, bn_beta, bn_mean, bn_var, out);
}

// round 15
// speedup vs baseline: 1.0888x; 1.0477x over previous
#include <cuda_runtime.h>

#define NV   13824   // D*H*W
#define HWV  576     // H*W

// ---------------- scratch (device globals; allocation-free) ----------------
__device__ __align__(16) float g_theta[NV * 64];
__device__ __align__(16) float g_phi[NV * 64];
__device__ __align__(16) float g_gval[NV * 64];
__device__ __align__(16) float g_f[NV * 72];    // [node][fam*24+col], holds exp(logit)
__device__ __align__(16) float g_y0[NV * 64];   // unnormalized exp-weighted sums
__device__ __align__(16) float g_y1[NV * 64];
__device__ __align__(16) float g_y2[NV * 64];
__device__ float g_es0[NV];                     // per-node partial exp sums
__device__ float g_es1[NV];
__device__ float g_es2[NV];
__device__ __align__(16) float g_cross[NV * 64];
__device__ __align__(16) float g_h[NV * 64];
__device__ __align__(16) float g_wT[64 * 192];  // [c][p*64+d]
__device__ float g_statS[32];   // [iter][group]
__device__ float g_statSS[32];

// ---------------- K0: one-time weight transposition (theta/phi/G only) ----------------
__global__ __launch_bounds__(256) void k_prep(
    const float* __restrict__ tw, const float* __restrict__ pw,
    const float* __restrict__ gw)
{
    int idx = blockIdx.x * 256 + threadIdx.x;
    if (idx < 12288) {
        int p = idx >> 12, rem = idx & 4095;
        int d = rem >> 6, c = rem & 63;
        const float* w = (p == 0) ? tw : (p == 1) ? pw : gw;
        g_wT[c * 192 + p * 64 + d] = w[d * 64 + c];
    }
}

// ---------------- K1: fused theta/phi/g projection (32 nodes/block) ----------------
__global__ __launch_bounds__(256) void k_proj(
    const float* __restrict__ x, int iter,
    const float* __restrict__ tb, const float* __restrict__ pb,
    const float* __restrict__ gb,
    const float* __restrict__ gng, const float* __restrict__ gnb)
{
    extern __shared__ float dsm[];
    float* hs = dsm;                  // [c][nl], stride 32 (2048)
    float* ws = dsm + 2048;           // [c][p*64+d], stride 192 (12288)
    float* sm_m  = dsm + 14336;       // 16
    float* sm_rs = dsm + 14352;       // 16

    const int t = threadIdx.x;
    const int n0 = blockIdx.x * 32;

    if (iter) {
        if (t < 16) {
            const float invc = 1.f / (4.f * NV);
            float m = g_statS[t] * invc;
            float var = g_statSS[t] * invc - m * m;
            sm_m[t] = m;
            sm_rs[t] = rsqrtf(var + 1e-5f);
        }
        __syncthreads();
    }
    if (blockIdx.x == 0 && t < 16) {
        g_statS [iter * 16 + t] = 0.f;
        g_statSS[iter * 16 + t] = 0.f;
    }

    if (iter == 0) {
        for (int v = t; v < 512; v += 256) {
            int c = v >> 3, nl4 = (v & 7) * 4;
            *(float4*)&hs[v * 4] = *(const float4*)&x[(size_t)c * NV + n0 + nl4];
        }
    } else {
        for (int v = t; v < 512; v += 256) {
            int c = v >> 3, nl4 = (v & 7) * 4;
            int g = c >> 2;
            size_t gi = (size_t)c * NV + n0 + nl4;
            float4 xv = *(const float4*)&x[gi];
            float4 cv = *(const float4*)&g_cross[gi];
            float sc = sm_rs[g] * gng[c];
            float off = gnb[c] - sm_m[g] * sc;
            float4 hv;
            hv.x = xv.x + cv.x * sc + off;
            hv.y = xv.y + cv.y * sc + off;
            hv.z = xv.z + cv.z * sc + off;
            hv.w = xv.w + cv.w * sc + off;
            *(float4*)&hs[v * 4] = hv;
            *(float4*)&g_h[gi] = hv;
        }
    }

    {
        const float4* wt4 = (const float4*)g_wT;
        float4* ws4 = (float4*)ws;
        for (int v = t; v < 3072; v += 256) ws4[v] = wt4[v];
    }
    __syncthreads();

    const int nl0 = (t & 7) * 4;
    const int d0  = (t >> 3) * 2;

    float acc[3][2][4];
    {
        const float* bs[3] = {tb, pb, gb};
        #pragma unroll
        for (int p = 0; p < 3; p++)
            #pragma unroll
            for (int di = 0; di < 2; di++) {
                float bb = bs[p][d0 + di];
                #pragma unroll
                for (int ni = 0; ni < 4; ni++) acc[p][di][ni] = bb;
            }
    }

    #pragma unroll 4
    for (int c = 0; c < 64; c++) {
        float4 hv = *(const float4*)&hs[c * 32 + nl0];
        float ha[4] = {hv.x, hv.y, hv.z, hv.w};
        #pragma unroll
        for (int p = 0; p < 3; p++) {
            float2 wv = *(const float2*)&ws[c * 192 + p * 64 + d0];
            #pragma unroll
            for (int ni = 0; ni < 4; ni++) {
                acc[p][0][ni] += ha[ni] * wv.x;
                acc[p][1][ni] += ha[ni] * wv.y;
            }
        }
    }

    float* outs[3] = {g_theta, g_phi, g_gval};
    #pragma unroll
    for (int p = 0; p < 3; p++)
        #pragma unroll
        for (int ni = 0; ni < 4; ni++)
            *(float2*)&outs[p][(size_t)(n0 + nl0 + ni) * 64 + d0] =
                make_float2(acc[p][0][ni], acc[p][1][ni]);
}

// line geometry: fam 0 = depth line (incl self), 1 = H line, 2 = W line
__device__ __forceinline__ void line_geom(int fam, int line, int& base, int& stride)
{
    if (fam == 0)      { base = line; stride = HWV; }
    else if (fam == 1) { base = (line / 24) * HWV + (line % 24); stride = 24; }
    else               { base = line * 24; stride = 1; }
}

// ---------------- K2: line grams -> exp(logits) to g_f ----------------
__global__ __launch_bounds__(64) void k_scores()
{
    __shared__ float th[24][68];
    __shared__ float ph[24][68];
    const int t = threadIdx.x;
    int base, stride;
    line_geom(blockIdx.y, blockIdx.x, base, stride);
    const int fam24 = blockIdx.y * 24;

    // float4 tile loads: 2 arrays x 384 float4s over 64 threads
    for (int v = t; v < 384; v += 64) {
        int p = v >> 4, d4 = (v & 15) * 4;
        size_t gi = (size_t)(base + p * stride) * 64 + d4;
        *(float4*)&th[p][d4] = *(const float4*)&g_theta[gi];
        *(float4*)&ph[p][d4] = *(const float4*)&g_phi[gi];
    }
    __syncthreads();

    const int r0 = (t >> 3) * 3;
    const int q0 = (t & 7) * 3;
    float acc[3][3] = {};
    #pragma unroll
    for (int cc = 0; cc < 16; cc++) {
        float4 tv[3], pv[3];
        #pragma unroll
        for (int r = 0; r < 3; r++) tv[r] = *(const float4*)&th[r0 + r][cc * 4];
        #pragma unroll
        for (int q = 0; q < 3; q++) pv[q] = *(const float4*)&ph[q0 + q][cc * 4];
        #pragma unroll
        for (int r = 0; r < 3; r++)
            #pragma unroll
            for (int q = 0; q < 3; q++)
                acc[r][q] += tv[r].x * pv[q].x + tv[r].y * pv[q].y +
                             tv[r].z * pv[q].z + tv[r].w * pv[q].w;
    }

    #pragma unroll
    for (int r = 0; r < 3; r++) {
        int node = base + (r0 + r) * stride;
        #pragma unroll
        for (int q = 0; q < 3; q++)
            g_f[(size_t)node * 72 + fam24 + q0 + q] = __expf(acc[r][q]);
    }
}

// ---------------- K3: unnormalized exp-weighted merge (per family) ----------------
__global__ __launch_bounds__(128) void k_merge()
{
    __shared__ float gs[24][68];
    __shared__ float as[24][28];   // 16B-aligned rows for float4 access
    const int t = threadIdx.x;
    int base, stride;
    line_geom(blockIdx.y, blockIdx.x, base, stride);
    const int fam = blockIdx.y;

    // g tile: float4 loads (384 float4s / 128 threads = 3 each)
    for (int v = t; v < 384; v += 128) {
        int p = v >> 4, d4 = (v & 15) * 4;
        *(float4*)&gs[p][d4] =
            *(const float4*)&g_gval[(size_t)(base + p * stride) * 64 + d4];
    }
    // exp weights: float4 loads from g_f (already exp'd), diag zeroed
    for (int v = t; v < 144; v += 128) {
        int p = v / 6, q4 = (v - p * 6) * 4;
        float4 fv = *(const float4*)&g_f[(size_t)(base + p * stride) * 72 + fam * 24 + q4];
        float e[4] = {fv.x, fv.y, fv.z, fv.w};
        #pragma unroll
        for (int c = 0; c < 4; c++) {
            int q = q4 + c;
            as[p][q] = (fam != 0 && q == p) ? 0.f : e[c];
        }
    }
    __syncthreads();

    if (t < 24) {
        float s = 0.f;
        #pragma unroll
        for (int q = 0; q < 24; q++) s += as[t][q];
        float* es = (fam == 0) ? g_es0 : (fam == 1) ? g_es1 : g_es2;
        es[base + t * stride] = s;
    }

    // merge GEMM: vectorized a-loads (float4), 42 LDS.128 total per thread
    const int rg = t >> 4;          // 8 row groups of 3 nodes
    const int d0 = (t & 15) * 4;    // 16 col groups of 4 dims
    float acc[3][4] = {};
    #pragma unroll
    for (int l4 = 0; l4 < 24; l4 += 4) {
        float av[3][4];
        #pragma unroll
        for (int r = 0; r < 3; r++)
            *(float4*)av[r] = *(const float4*)&as[rg * 3 + r][l4];
        #pragma unroll
        for (int j = 0; j < 4; j++) {
            float4 gv = *(const float4*)&gs[l4 + j][d0];
            #pragma unroll
            for (int r = 0; r < 3; r++) {
                float a = av[r][j];
                acc[r][0] += a * gv.x; acc[r][1] += a * gv.y;
                acc[r][2] += a * gv.z; acc[r][3] += a * gv.w;
            }
        }
    }
    float* yout = (fam == 0) ? g_y0 : (fam == 1) ? g_y1 : g_y2;
    #pragma unroll
    for (int r = 0; r < 3; r++) {
        int node = base + (rg * 3 + r) * stride;
        *(float4*)&yout[(size_t)node * 64 + d0] =
            make_float4(acc[r][0], acc[r][1], acc[r][2], acc[r][3]);
    }
}

// ---------------- K4: normalize + output projection + GroupNorm stats ----------------
__global__ __launch_bounds__(256) void k_cross(
    const float* __restrict__ rw, const float* __restrict__ rb, int iter)
{
    __shared__ float ys[32 * 68];   // [nl][g]
    __shared__ float rs[64 * 68];   // [c][g]
    __shared__ float inv_s[32];
    const int t = threadIdx.x;
    const int n0 = blockIdx.x * 32;

    if (t < 32) {
        int n = n0 + t;
        inv_s[t] = 1.f / (g_es0[n] + g_es1[n] + g_es2[n]);
    }
    __syncthreads();

    for (int v = t; v < 512; v += 256) {
        int nl = v >> 4, g4 = (v & 15) * 4;
        size_t gi = (size_t)(n0 + nl) * 64 + g4;
        float inv = inv_s[nl];
        float4 a = *(const float4*)&g_y0[gi];
        float4 b = *(const float4*)&g_y1[gi];
        float4 c = *(const float4*)&g_y2[gi];
        *(float4*)&ys[nl * 68 + g4] =
            make_float4((a.x + b.x + c.x) * inv, (a.y + b.y + c.y) * inv,
                        (a.z + b.z + c.z) * inv, (a.w + b.w + c.w) * inv);
    }
    for (int v = t; v < 1024; v += 256) {
        int c = v >> 4, g4 = (v & 15) * 4;
        *(float4*)&rs[c * 68 + g4] = *(const float4*)&rw[c * 64 + g4];
    }
    __syncthreads();

    const int q  = t & 7;            // node lane: nodes q, q+8, q+16, q+24
    const int c0 = (t >> 3) * 2;     // channel pair
    float acc[2][4];
    #pragma unroll
    for (int ci = 0; ci < 2; ci++) {
        float bb = rb[c0 + ci];
        #pragma unroll
        for (int ni = 0; ni < 4; ni++) acc[ci][ni] = bb;
    }

    #pragma unroll 4
    for (int g4 = 0; g4 < 64; g4 += 4) {
        float4 ra = *(const float4*)&rs[c0 * 68 + g4];
        float4 rbv = *(const float4*)&rs[(c0 + 1) * 68 + g4];
        #pragma unroll
        for (int ni = 0; ni < 4; ni++) {
            float4 yv = *(const float4*)&ys[(q + 8 * ni) * 68 + g4];
            acc[0][ni] += ra.x * yv.x + ra.y * yv.y + ra.z * yv.z + ra.w * yv.w;
            acc[1][ni] += rbv.x * yv.x + rbv.y * yv.y + rbv.z * yv.z + rbv.w * yv.w;
        }
    }

    float s = 0.f, ss = 0.f;
    #pragma unroll
    for (int ci = 0; ci < 2; ci++) {
        #pragma unroll
        for (int ni = 0; ni < 4; ni++) {
            g_cross[(size_t)(c0 + ci) * NV + n0 + q + 8 * ni] = acc[ci][ni];
            s += acc[ci][ni];
            ss += acc[ci][ni] * acc[ci][ni];
        }
    }
    #pragma unroll
    for (int o = 8; o; o >>= 1) {
        s  += __shfl_xor_sync(0xffffffffu, s, o);
        ss += __shfl_xor_sync(0xffffffffu, ss, o);
    }
    if ((t & 15) == 0) {
        atomicAdd(&g_statS [iter * 16 + (t >> 4)], s);
        atomicAdd(&g_statSS[iter * 16 + (t >> 4)], ss);
    }
}

// ---------------- K5: final GN apply + residual + BN + ReLU (float4) ----------------
__global__ __launch_bounds__(256) void k_final(
    const float* __restrict__ gng, const float* __restrict__ gnb,
    const float* __restrict__ bng, const float* __restrict__ bnb,
    const float* __restrict__ bnm, const float* __restrict__ bnv,
    float* __restrict__ out)
{
    int i4 = blockIdx.x * 256 + threadIdx.x;
    int idx = i4 * 4;
    int c = idx / NV;
    int g = c >> 2;
    const float invc = 1.f / (4.f * NV);
    float m   = g_statS [16 + g] * invc;
    float var = g_statSS[16 + g] * invc - m * m;
    float rstd = rsqrtf(var + 1e-5f);
    float ga = gng[c], gb = gnb[c];
    float bsc = rsqrtf(bnv[c] + 1e-5f) * bng[c];
    float bm = bnm[c], bb = bnb[c];

    float4 hv = *(const float4*)&g_h[idx];
    float4 cv = *(const float4*)&g_cross[idx];
    float ha[4] = {hv.x, hv.y, hv.z, hv.w};
    float ca[4] = {cv.x, cv.y, cv.z, cv.w};
    float oa[4];
    #pragma unroll
    for (int i = 0; i < 4; i++) {
        float v = ha[i] + (ca[i] - m) * rstd * ga + gb;
        float o = (v - bm) * bsc + bb;
        oa[i] = fmaxf(o, 0.f);
    }
    *(float4*)&out[idx] = make_float4(oa[0], oa[1], oa[2], oa[3]);
}

// ---------------- launch ----------------
extern "C" void kernel_launch(void* const* d_in, const int* in_sizes, int n_in,
                              void* d_out, int out_size)
{
    const float* x        = (const float*)d_in[0];
    // d_in[1] = nbr_idx (int32) — neighbor structure derived analytically, unused
    const float* phi_w    = (const float*)d_in[2];
    const float* phi_b    = (const float*)d_in[3];
    const float* theta_w  = (const float*)d_in[4];
    const float* theta_b  = (const float*)d_in[5];
    const float* G_w      = (const float*)d_in[6];
    const float* G_b      = (const float*)d_in[7];
    const float* r_w      = (const float*)d_in[8];
    const float* r_b      = (const float*)d_in[9];
    const float* gn_gamma = (const float*)d_in[10];
    const float* gn_beta  = (const float*)d_in[11];
    const float* bn_gamma = (const float*)d_in[12];
    const float* bn_beta  = (const float*)d_in[13];
    const float* bn_mean  = (const float*)d_in[14];
    const float* bn_var   = (const float*)d_in[15];
    float* out = (float*)d_out;

    const int proj_smem = (2048 + 12288 + 32) * sizeof(float);  // 57472 B
    static bool attr_set = false;
    if (!attr_set) {
        cudaFuncSetAttribute(k_proj, cudaFuncAttributeMaxDynamicSharedMemorySize, proj_smem);
        attr_set = true;
    }

    k_prep<<<48, 256>>>(theta_w, phi_w, G_w);
    dim3 gline(576, 3);
    for (int it = 0; it < 2; it++) {
        k_proj<<<NV / 32, 256, proj_smem>>>(x, it, theta_b, phi_b, G_b,
                                            gn_gamma, gn_beta);
        k_scores<<<gline, 64>>>();
        k_merge<<<gline, 128>>>();
        k_cross<<<NV / 32, 256>>>(r_w, r_b, it);
    }
    k_final<<<(64 * NV) / 1024, 256>>>(gn_gamma + 64, gn_beta + 64,
                                       bn_gamma, bn_beta, bn_mean, bn_var, out);
}

// round 17
// speedup vs baseline: 1.1152x; 1.0243x over previous
#include <cuda_runtime.h>

#define NV   13824   // D*H*W
#define HWV  576     // H*W

// ---------------- scratch (device globals; allocation-free) ----------------
__device__ __align__(16) float g_theta[NV * 64];
__device__ __align__(16) float g_phi[NV * 64];
__device__ __align__(16) float g_gval[NV * 64];
__device__ __align__(16) float g_f[NV * 72];    // [node][fam*24+col], holds exp(logit)
__device__ __align__(16) float g_y0[NV * 64];   // unnormalized exp-weighted sums
__device__ __align__(16) float g_y1[NV * 64];
__device__ __align__(16) float g_y2[NV * 64];
__device__ float g_es0[NV];                     // per-node partial exp sums
__device__ float g_es1[NV];
__device__ float g_es2[NV];
__device__ __align__(16) float g_cross[NV * 64];
__device__ __align__(16) float g_h[NV * 64];
__device__ __align__(16) float g_wT[64 * 192];  // [c][p*64+d]
__device__ float g_statS[32];   // [iter][group]
__device__ float g_statSS[32];

// ---------------- K0: one-time weight transposition (theta/phi/G only) ----------------
__global__ __launch_bounds__(256) void k_prep(
    const float* __restrict__ tw, const float* __restrict__ pw,
    const float* __restrict__ gw)
{
    int idx = blockIdx.x * 256 + threadIdx.x;
    if (idx < 12288) {
        int p = idx >> 12, rem = idx & 4095;
        int d = rem >> 6, c = rem & 63;
        const float* w = (p == 0) ? tw : (p == 1) ? pw : gw;
        g_wT[c * 192 + p * 64 + d] = w[d * 64 + c];
    }
}

// ---------------- K1: fused theta/phi/g projection (32 nodes/block) ----------------
__global__ __launch_bounds__(256) void k_proj(
    const float* __restrict__ x, int iter,
    const float* __restrict__ tb, const float* __restrict__ pb,
    const float* __restrict__ gb,
    const float* __restrict__ gng, const float* __restrict__ gnb)
{
    extern __shared__ float dsm[];
    float* hs = dsm;                  // [c][nl], stride 32 (2048)
    float* ws = dsm + 2048;           // [c][p*64+d], stride 192 (12288)
    float* sm_m  = dsm + 14336;       // 16
    float* sm_rs = dsm + 14352;       // 16

    const int t = threadIdx.x;
    const int n0 = blockIdx.x * 32;

    if (iter) {
        if (t < 16) {
            const float invc = 1.f / (4.f * NV);
            float m = g_statS[t] * invc;
            float var = g_statSS[t] * invc - m * m;
            sm_m[t] = m;
            sm_rs[t] = rsqrtf(var + 1e-5f);
        }
        __syncthreads();
    }
    if (blockIdx.x == 0 && t < 16) {
        g_statS [iter * 16 + t] = 0.f;
        g_statSS[iter * 16 + t] = 0.f;
    }

    if (iter == 0) {
        for (int v = t; v < 512; v += 256) {
            int c = v >> 3, nl4 = (v & 7) * 4;
            *(float4*)&hs[v * 4] = *(const float4*)&x[(size_t)c * NV + n0 + nl4];
        }
    } else {
        for (int v = t; v < 512; v += 256) {
            int c = v >> 3, nl4 = (v & 7) * 4;
            int g = c >> 2;
            size_t gi = (size_t)c * NV + n0 + nl4;
            float4 xv = *(const float4*)&x[gi];
            float4 cv = *(const float4*)&g_cross[gi];
            float sc = sm_rs[g] * gng[c];
            float off = gnb[c] - sm_m[g] * sc;
            float4 hv;
            hv.x = xv.x + cv.x * sc + off;
            hv.y = xv.y + cv.y * sc + off;
            hv.z = xv.z + cv.z * sc + off;
            hv.w = xv.w + cv.w * sc + off;
            *(float4*)&hs[v * 4] = hv;
            *(float4*)&g_h[gi] = hv;
        }
    }

    {
        const float4* wt4 = (const float4*)g_wT;
        float4* ws4 = (float4*)ws;
        for (int v = t; v < 3072; v += 256) ws4[v] = wt4[v];
    }
    __syncthreads();

    const int nl0 = (t & 7) * 4;
    const int d0  = (t >> 3) * 2;

    float acc[3][2][4];
    {
        const float* bs[3] = {tb, pb, gb};
        #pragma unroll
        for (int p = 0; p < 3; p++)
            #pragma unroll
            for (int di = 0; di < 2; di++) {
                float bb = bs[p][d0 + di];
                #pragma unroll
                for (int ni = 0; ni < 4; ni++) acc[p][di][ni] = bb;
            }
    }

    #pragma unroll 4
    for (int c = 0; c < 64; c++) {
        float4 hv = *(const float4*)&hs[c * 32 + nl0];
        float ha[4] = {hv.x, hv.y, hv.z, hv.w};
        #pragma unroll
        for (int p = 0; p < 3; p++) {
            float2 wv = *(const float2*)&ws[c * 192 + p * 64 + d0];
            #pragma unroll
            for (int ni = 0; ni < 4; ni++) {
                acc[p][0][ni] += ha[ni] * wv.x;
                acc[p][1][ni] += ha[ni] * wv.y;
            }
        }
    }

    float* outs[3] = {g_theta, g_phi, g_gval};
    #pragma unroll
    for (int p = 0; p < 3; p++)
        #pragma unroll
        for (int ni = 0; ni < 4; ni++)
            *(float2*)&outs[p][(size_t)(n0 + nl0 + ni) * 64 + d0] =
                make_float2(acc[p][0][ni], acc[p][1][ni]);
}

// line geometry: fam 0 = depth line (incl self), 1 = H line, 2 = W line
__device__ __forceinline__ void line_geom(int fam, int line, int& base, int& stride)
{
    if (fam == 0)      { base = line; stride = HWV; }
    else if (fam == 1) { base = (line / 24) * HWV + (line % 24); stride = 24; }
    else               { base = line * 24; stride = 1; }
}

// ---------------- K2: line grams -> exp(logits) to g_f (2 lines/block) ----------------
__global__ __launch_bounds__(128) void k_scores()
{
    __shared__ float th[2][24][68];
    __shared__ float ph[2][24][68];
    const int t = threadIdx.x;
    const int fam = blockIdx.y;
    const int fam24 = fam * 24;
    int base[2], stride;
    line_geom(fam, blockIdx.x * 2 + 0, base[0], stride);
    { int s1; line_geom(fam, blockIdx.x * 2 + 1, base[1], s1); }

    // float4 tile loads: 2 lines x 2 arrays x 384 float4s
    for (int v = t; v < 768; v += 128) {
        int li = v / 384, rem = v - li * 384;
        int p = rem >> 4, d4 = (rem & 15) * 4;
        size_t gi = (size_t)(base[li] + p * stride) * 64 + d4;
        *(float4*)&th[li][p][d4] = *(const float4*)&g_theta[gi];
        *(float4*)&ph[li][p][d4] = *(const float4*)&g_phi[gi];
    }
    __syncthreads();

    const int li = t >> 6, tt = t & 63;
    const int r0 = (tt >> 3) * 3;
    const int q0 = (tt & 7) * 3;
    float acc[3][3] = {};
    #pragma unroll
    for (int cc = 0; cc < 16; cc++) {
        float4 tv[3], pv[3];
        #pragma unroll
        for (int r = 0; r < 3; r++) tv[r] = *(const float4*)&th[li][r0 + r][cc * 4];
        #pragma unroll
        for (int q = 0; q < 3; q++) pv[q] = *(const float4*)&ph[li][q0 + q][cc * 4];
        #pragma unroll
        for (int r = 0; r < 3; r++)
            #pragma unroll
            for (int q = 0; q < 3; q++)
                acc[r][q] += tv[r].x * pv[q].x + tv[r].y * pv[q].y +
                             tv[r].z * pv[q].z + tv[r].w * pv[q].w;
    }

    #pragma unroll
    for (int r = 0; r < 3; r++) {
        int node = base[li] + (r0 + r) * stride;
        #pragma unroll
        for (int q = 0; q < 3; q++)
            g_f[(size_t)node * 72 + fam24 + q0 + q] = __expf(acc[r][q]);
    }
}

// ---------------- K3: unnormalized exp-weighted merge (2 lines/block) ----------------
// Each half-block handles one line: 64 threads = 4 row-groups(6 rows) x 16 dim-groups(4).
__global__ __launch_bounds__(128) void k_merge()
{
    __shared__ float gs[2][24][68];
    __shared__ float as[2][24][28];
    const int t = threadIdx.x;
    const int fam = blockIdx.y;
    int base[2], stride;
    line_geom(fam, blockIdx.x * 2 + 0, base[0], stride);
    { int s1; line_geom(fam, blockIdx.x * 2 + 1, base[1], s1); }

    // g tiles: 2 x 384 float4s
    for (int v = t; v < 768; v += 128) {
        int li = v / 384, rem = v - li * 384;
        int p = rem >> 4, d4 = (rem & 15) * 4;
        *(float4*)&gs[li][p][d4] =
            *(const float4*)&g_gval[(size_t)(base[li] + p * stride) * 64 + d4];
    }
    // exp weights: 2 x 144 float4s, diag zeroed
    for (int v = t; v < 288; v += 128) {
        int li = v / 144, rem = v - li * 144;
        int p = rem / 6, q4 = (rem - p * 6) * 4;
        float4 fv = *(const float4*)&g_f[(size_t)(base[li] + p * stride) * 72 + fam * 24 + q4];
        float e[4] = {fv.x, fv.y, fv.z, fv.w};
        #pragma unroll
        for (int c = 0; c < 4; c++) {
            int q = q4 + c;
            as[li][p][q] = (fam != 0 && q == p) ? 0.f : e[c];
        }
    }
    __syncthreads();

    if (t < 48) {
        int li = t / 24, p = t - li * 24;
        float s = 0.f;
        #pragma unroll
        for (int q = 0; q < 24; q++) s += as[li][p][q];
        float* es = (fam == 0) ? g_es0 : (fam == 1) ? g_es1 : g_es2;
        es[base[li] + p * stride] = s;
    }

    const int li = t >> 6, tt = t & 63;
    const int rg = tt >> 4;          // 4 row groups of 6 nodes
    const int d0 = (tt & 15) * 4;    // 16 dim groups of 4
    float acc[6][4] = {};
    #pragma unroll
    for (int l4 = 0; l4 < 24; l4 += 4) {
        float av[6][4];
        #pragma unroll
        for (int r = 0; r < 6; r++)
            *(float4*)av[r] = *(const float4*)&as[li][rg * 6 + r][l4];
        #pragma unroll
        for (int j = 0; j < 4; j++) {
            float4 gv = *(const float4*)&gs[li][l4 + j][d0];
            #pragma unroll
            for (int r = 0; r < 6; r++) {
                float a = av[r][j];
                acc[r][0] += a * gv.x; acc[r][1] += a * gv.y;
                acc[r][2] += a * gv.z; acc[r][3] += a * gv.w;
            }
        }
    }
    float* yout = (fam == 0) ? g_y0 : (fam == 1) ? g_y1 : g_y2;
    #pragma unroll
    for (int r = 0; r < 6; r++) {
        int node = base[li] + (rg * 6 + r) * stride;
        *(float4*)&yout[(size_t)node * 64 + d0] =
            make_float4(acc[r][0], acc[r][1], acc[r][2], acc[r][3]);
    }
}

// ---------------- K4: normalize + output projection + GroupNorm stats ----------------
__global__ __launch_bounds__(256) void k_cross(
    const float* __restrict__ rw, const float* __restrict__ rb, int iter)
{
    __shared__ float ys[32 * 68];   // [nl][g]
    __shared__ float rs[64 * 68];   // [c][g]
    __shared__ float inv_s[32];
    const int t = threadIdx.x;
    const int n0 = blockIdx.x * 32;

    if (t < 32) {
        int n = n0 + t;
        inv_s[t] = 1.f / (g_es0[n] + g_es1[n] + g_es2[n]);
    }
    __syncthreads();

    for (int v = t; v < 512; v += 256) {
        int nl = v >> 4, g4 = (v & 15) * 4;
        size_t gi = (size_t)(n0 + nl) * 64 + g4;
        float inv = inv_s[nl];
        float4 a = *(const float4*)&g_y0[gi];
        float4 b = *(const float4*)&g_y1[gi];
        float4 c = *(const float4*)&g_y2[gi];
        *(float4*)&ys[nl * 68 + g4] =
            make_float4((a.x + b.x + c.x) * inv, (a.y + b.y + c.y) * inv,
                        (a.z + b.z + c.z) * inv, (a.w + b.w + c.w) * inv);
    }
    for (int v = t; v < 1024; v += 256) {
        int c = v >> 4, g4 = (v & 15) * 4;
        *(float4*)&rs[c * 68 + g4] = *(const float4*)&rw[c * 64 + g4];
    }
    __syncthreads();

    const int q  = t & 7;            // node lane: nodes q, q+8, q+16, q+24
    const int c0 = (t >> 3) * 2;     // channel pair
    float acc[2][4];
    #pragma unroll
    for (int ci = 0; ci < 2; ci++) {
        float bb = rb[c0 + ci];
        #pragma unroll
        for (int ni = 0; ni < 4; ni++) acc[ci][ni] = bb;
    }

    #pragma unroll 4
    for (int g4 = 0; g4 < 64; g4 += 4) {
        float4 ra = *(const float4*)&rs[c0 * 68 + g4];
        float4 rbv = *(const float4*)&rs[(c0 + 1) * 68 + g4];
        #pragma unroll
        for (int ni = 0; ni < 4; ni++) {
            float4 yv = *(const float4*)&ys[(q + 8 * ni) * 68 + g4];
            acc[0][ni] += ra.x * yv.x + ra.y * yv.y + ra.z * yv.z + ra.w * yv.w;
            acc[1][ni] += rbv.x * yv.x + rbv.y * yv.y + rbv.z * yv.z + rbv.w * yv.w;
        }
    }

    float s = 0.f, ss = 0.f;
    #pragma unroll
    for (int ci = 0; ci < 2; ci++) {
        #pragma unroll
        for (int ni = 0; ni < 4; ni++) {
            g_cross[(size_t)(c0 + ci) * NV + n0 + q + 8 * ni] = acc[ci][ni];
            s += acc[ci][ni];
            ss += acc[ci][ni] * acc[ci][ni];
        }
    }
    #pragma unroll
    for (int o = 8; o; o >>= 1) {
        s  += __shfl_xor_sync(0xffffffffu, s, o);
        ss += __shfl_xor_sync(0xffffffffu, ss, o);
    }
    if ((t & 15) == 0) {
        atomicAdd(&g_statS [iter * 16 + (t >> 4)], s);
        atomicAdd(&g_statSS[iter * 16 + (t >> 4)], ss);
    }
}

// ---------------- K5: final GN apply + residual + BN + ReLU (float4) ----------------
__global__ __launch_bounds__(256) void k_final(
    const float* __restrict__ gng, const float* __restrict__ gnb,
    const float* __restrict__ bng, const float* __restrict__ bnb,
    const float* __restrict__ bnm, const float* __restrict__ bnv,
    float* __restrict__ out)
{
    int i4 = blockIdx.x * 256 + threadIdx.x;
    int idx = i4 * 4;
    int c = idx / NV;
    int g = c >> 2;
    const float invc = 1.f / (4.f * NV);
    float m   = g_statS [16 + g] * invc;
    float var = g_statSS[16 + g] * invc - m * m;
    float rstd = rsqrtf(var + 1e-5f);
    float ga = gng[c], gb = gnb[c];
    float bsc = rsqrtf(bnv[c] + 1e-5f) * bng[c];
    float bm = bnm[c], bb = bnb[c];

    float4 hv = *(const float4*)&g_h[idx];
    float4 cv = *(const float4*)&g_cross[idx];
    float ha[4] = {hv.x, hv.y, hv.z, hv.w};
    float ca[4] = {cv.x, cv.y, cv.z, cv.w};
    float oa[4];
    #pragma unroll
    for (int i = 0; i < 4; i++) {
        float v = ha[i] + (ca[i] - m) * rstd * ga + gb;
        float o = (v - bm) * bsc + bb;
        oa[i] = fmaxf(o, 0.f);
    }
    *(float4*)&out[idx] = make_float4(oa[0], oa[1], oa[2], oa[3]);
}

// ---------------- launch ----------------
extern "C" void kernel_launch(void* const* d_in, const int* in_sizes, int n_in,
                              void* d_out, int out_size)
{
    const float* x        = (const float*)d_in[0];
    // d_in[1] = nbr_idx (int32) — neighbor structure derived analytically, unused
    const float* phi_w    = (const float*)d_in[2];
    const float* phi_b    = (const float*)d_in[3];
    const float* theta_w  = (const float*)d_in[4];
    const float* theta_b  = (const float*)d_in[5];
    const float* G_w      = (const float*)d_in[6];
    const float* G_b      = (const float*)d_in[7];
    const float* r_w      = (const float*)d_in[8];
    const float* r_b      = (const float*)d_in[9];
    const float* gn_gamma = (const float*)d_in[10];
    const float* gn_beta  = (const float*)d_in[11];
    const float* bn_gamma = (const float*)d_in[12];
    const float* bn_beta  = (const float*)d_in[13];
    const float* bn_mean  = (const float*)d_in[14];
    const float* bn_var   = (const float*)d_in[15];
    float* out = (float*)d_out;

    const int proj_smem = (2048 + 12288 + 32) * sizeof(float);  // 57472 B
    static bool attr_set = false;
    if (!attr_set) {
        cudaFuncSetAttribute(k_proj, cudaFuncAttributeMaxDynamicSharedMemorySize, proj_smem);
        attr_set = true;
    }

    k_prep<<<48, 256>>>(theta_w, phi_w, G_w);
    dim3 gline(288, 3);
    for (int it = 0; it < 2; it++) {
        k_proj<<<NV / 32, 256, proj_smem>>>(x, it, theta_b, phi_b, G_b,
                                            gn_gamma, gn_beta);
        k_scores<<<gline, 128>>>();
        k_merge<<<gline, 128>>>();
        k_cross<<<NV / 32, 256>>>(r_w, r_b, it);
    }
    k_final<<<(64 * NV) / 1024, 256>>>(gn_gamma + 64, gn_beta + 64,
                                       bn_gamma, bn_beta, bn_mean, bn_var, out);
}